// round 15
// baseline (speedup 1.0000x reference)
#include <cuda_runtime.h>
#include <cstdint>

#define NN 1024
#define BB 8
#define EE 512
#define HH 8
#define DD 64
#define L2E 1.4426950408889634f
#define QS (L2E * 0.125f)

// Scratch (device globals: allocation-free per harness rules)
__device__ uint32_t g_Apk[8192 * 512];        // nodes, A-frag packed tf32
__device__ uint32_t g_Wpk[4 * 262144];        // W*, B-frag packed (unpaired)
__device__ uint32_t g_Qu [BB * HH * NN * DD]; // Q tf32, prescaled, [bh][n][d]
__device__ uint32_t g_Kpk[BB * HH * 65536];   // K B-frag packed, kt-PAIRED
__device__ uint32_t g_Vpk[BB * HH * 65536];   // V B-frag packed, j-perm + nt-PAIRED
__device__ uint32_t g_Attu[NN * BB * EE];     // attn out, tf32 bits, [n][b][e]

// ---------------------------------------------------------------------------
// helpers
// ---------------------------------------------------------------------------
__device__ __forceinline__ uint32_t f2tf(float f) {
    uint32_t r;
    asm("cvt.rna.tf32.f32 %0, %1;" : "=r"(r) : "f"(f));
    return r;
}
__device__ __forceinline__ float ex2f(float x) {
    float r;
    asm("ex2.approx.f32 %0, %1;" : "=f"(r) : "f"(x));
    return r;
}
__device__ __forceinline__ void mma8(float* d, const uint32_t* a,
                                     uint32_t b0, uint32_t b1) {
    asm volatile(
        "mma.sync.aligned.m16n8k8.row.col.f32.tf32.tf32.f32 "
        "{%0,%1,%2,%3}, {%4,%5,%6,%7}, {%8,%9}, {%0,%1,%2,%3};"
        : "+f"(d[0]), "+f"(d[1]), "+f"(d[2]), "+f"(d[3])
        : "r"(a[0]), "r"(a[1]), "r"(a[2]), "r"(a[3]), "r"(b0), "r"(b1));
}
__device__ __forceinline__ uint32_t smaddr(const void* p) {
    uint32_t a;
    asm("{ .reg .u64 t; cvta.to.shared.u64 t, %1; cvt.u32.u64 %0, t; }" : "=r"(a) : "l"(p));
    return a;
}
__device__ __forceinline__ void cpa16(uint32_t s, const void* g) {
    asm volatile("cp.async.ca.shared.global [%0], [%1], 16;" :: "r"(s), "l"(g) : "memory");
}
#define CPA_COMMIT() asm volatile("cp.async.commit_group;" ::: "memory")
#define CPA_WAIT0()  asm volatile("cp.async.wait_group 0;" ::: "memory")

// ===========================================================================
// Pre-pack kernels
// ===========================================================================
__global__ void __launch_bounds__(256) prepack_A(const float* __restrict__ src)
{
    const int t    = blockIdx.x * 256 + threadIdx.x;
    const int lane = t & 31;
    const int tile = t >> 5;
    const int mt = tile >> 6, kt = tile & 63;
    const int g = lane >> 2, c = lane & 3;
    const float* s = src + (size_t)(mt * 16 + g) * 512 + kt * 8 + c;
    uint4 o;
    o.x = f2tf(s[0]);
    o.y = f2tf(s[8 * 512]);
    o.z = f2tf(s[4]);
    o.w = f2tf(s[8 * 512 + 4]);
    *(uint4*)&g_Apk[(size_t)tile * 128 + lane * 4] = o;
}

__global__ void __launch_bounds__(256) prepack_W(
    const float* __restrict__ Wq, const float* __restrict__ Wk,
    const float* __restrict__ Wv, const float* __restrict__ Wo)
{
    const int which = blockIdx.y;
    const float* __restrict__ W =
        which == 0 ? Wq : which == 1 ? Wk : which == 2 ? Wv : Wo;
    const int t    = blockIdx.x * 256 + threadIdx.x;
    const int lane = t & 31;
    const int tile = t >> 5;
    const int nt = tile >> 6, kt = tile & 63;
    const int g = lane >> 2, c = lane & 3;
    const float* s = W + (size_t)(nt * 8 + g) * 512 + kt * 8 + c;
    uint2 o = make_uint2(f2tf(s[0]), f2tf(s[4]));
    *(uint2*)&g_Wpk[(size_t)which * 262144 + tile * 64 + lane * 2] = o;
}

// ===========================================================================
// QKV GEMM: R9-exact mainloop; epilogue -> g_Qu / paired g_Kpk / paired g_Vpk
// ===========================================================================
#define QKV_BYTES 65536

__global__ void __launch_bounds__(256) gemm_qkv(
    const float* __restrict__ bq, const float* __restrict__ bk,
    const float* __restrict__ bv)
{
    extern __shared__ uint32_t s[];
    const int tid   = threadIdx.x;
    const int which = blockIdx.y >> 2;
    const int c0t   = (blockIdx.y & 3) * 16;
    const int r0t   = blockIdx.x * 8;
    const uint32_t* __restrict__ Wg = g_Wpk + (size_t)which * 262144;
    const float* __restrict__ bias = which == 0 ? bq : which == 1 ? bk : bv;

    const int w = tid >> 5, lane = tid & 31;
    const int g = lane >> 2, c = lane & 3;
    const int wm = w & 3, wn = w >> 2;

    auto stage = [&](int kc, int buf) {
        const uint32_t ab = smaddr(s) + buf * 32768;
        const uint32_t bb = ab + 16384;
#pragma unroll
        for (int u = 0; u < 4; u++) {
            const int ua = u * 256 + tid;
            const int sa = ua >> 7, oa = ua & 127;
            cpa16(ab + ua * 16,
                  g_Apk + ((size_t)(r0t + sa) * 64 + kc * 4) * 128 + oa * 4);
            const int sb = ua >> 6, ob = ua & 63;
            cpa16(bb + ua * 16,
                  Wg + ((size_t)(c0t + sb) * 64 + kc * 4) * 64 + ob * 4);
        }
        CPA_COMMIT();
    };

    float acc[2][8][4];
#pragma unroll
    for (int mf = 0; mf < 2; mf++)
#pragma unroll
        for (int nt = 0; nt < 8; nt++)
#pragma unroll
            for (int e = 0; e < 4; e++) acc[mf][nt][e] = 0.f;

    stage(0, 0);

    for (int kc = 0; kc < 16; kc++) {
        CPA_WAIT0();
        __syncthreads();
        if (kc < 15) stage(kc + 1, (kc + 1) & 1);

        const uint32_t* As = s + (kc & 1) * 8192;
        const uint32_t* Bs = As + 4096;
#pragma unroll
        for (int kt = 0; kt < 4; kt++) {
            uint4 a0 = *(const uint4*)&As[((wm * 2 + 0) * 4 + kt) * 128 + lane * 4];
            uint4 a1 = *(const uint4*)&As[((wm * 2 + 1) * 4 + kt) * 128 + lane * 4];
#pragma unroll
            for (int nt = 0; nt < 8; nt++) {
                uint2 bb = *(const uint2*)&Bs[((wn * 8 + nt) * 4 + kt) * 64 + lane * 2];
                mma8(acc[0][nt], (const uint32_t*)&a0, bb.x, bb.y);
                mma8(acc[1][nt], (const uint32_t*)&a1, bb.x, bb.y);
            }
        }
    }

    const int r0 = r0t * 16, c0 = c0t * 8;
#pragma unroll
    for (int nt = 0; nt < 8; nt++) {
        const int col = c0 + 64 * wn + 8 * nt + 2 * c;
        float2 bb = *(const float2*)&bias[col];
#pragma unroll
        for (int mf = 0; mf < 2; mf++) {
#pragma unroll
            for (int rh = 0; rh < 2; rh++) {
                const int row = r0 + 32 * wm + 16 * mf + g + 8 * rh;
                float2 v = make_float2(acc[mf][nt][2 * rh] + bb.x,
                                       acc[mf][nt][2 * rh + 1] + bb.y);
                const int i = row >> 3, bq2 = row & 7;
                const int hh = col >> 6, d = col & 63;
                if (which == 0) {
                    uint2 t = make_uint2(f2tf(v.x * QS), f2tf(v.y * QS));
                    *(uint2*)&g_Qu[(((size_t)(bq2 * HH + hh)) * NN + i) * DD + d] = t;
                } else if (which == 1) {
                    // K kt-paired: lane=(i&7)*4+(d&3); d+1 -> +4 words
                    uint32_t* dst = g_Kpk + (size_t)(bq2 * HH + hh) * 65536;
                    uint32_t w0 = (uint32_t)(((i >> 3) * 4 + (d >> 4)) * 128
                                 + ((i & 7) * 4 + (d & 3)) * 4
                                 + ((d >> 3) & 1) * 2 + ((d >> 2) & 1));
                    dst[w0]     = f2tf(v.x);
                    dst[w0 + 4] = f2tf(v.y);
                } else {
                    // V j-perm + nt-paired: lane=(d&7)*4+((i&7)>>1); d+1 -> +16
                    uint32_t* dst = g_Vpk + (size_t)(bq2 * HH + hh) * 65536;
                    uint32_t w0 = (uint32_t)(((i >> 3) * 4 + (d >> 4)) * 128
                                 + ((d & 7) * 4 + ((i & 7) >> 1)) * 4
                                 + ((d >> 3) & 1) * 2 + (i & 1));
                    dst[w0]      = f2tf(v.x);
                    dst[w0 + 16] = f2tf(v.y);
                }
            }
        }
    }
}

// ===========================================================================
// Attention: BARRIER-FREE. B-fragments read directly from packed gmem via
// LDG.128 (contiguous 512B per warp-instruction; L1-hit after first warp).
// No smem, no cp.async, no __syncthreads -> warps desync and interleave
// MMA phases with exp epilogues across the SM.
// ===========================================================================
__global__ void __launch_bounds__(128) attn_mma(
    const float* __restrict__ edges, const float* __restrict__ rel)
{
    const int tid  = threadIdx.x;
    const int w    = tid >> 5;
    const int lane = tid & 31;
    const int g    = lane >> 2;
    const int c    = lane & 3;
    const int bh   = blockIdx.y, b = bh >> 3, h = bh & 7;
    const int i0   = blockIdx.x * 128;
    const float rbl2e = rel[h] * L2E;

    const uint32_t* Qb = g_Qu + ((size_t)bh * NN + i0 + 32 * w) * DD;
    uint32_t qa[2][8][4];
#pragma unroll
    for (int mf = 0; mf < 2; mf++) {
        const uint32_t* Qm = Qb + 16 * mf * DD;
#pragma unroll
        for (int kt = 0; kt < 8; kt++) {
            qa[mf][kt][0] = Qm[g * 64 + 8 * kt + c];
            qa[mf][kt][1] = Qm[(g + 8) * 64 + 8 * kt + c];
            qa[mf][kt][2] = Qm[g * 64 + 8 * kt + c + 4];
            qa[mf][kt][3] = Qm[(g + 8) * 64 + 8 * kt + c + 4];
        }
    }

    float oacc[2][8][4];
#pragma unroll
    for (int mf = 0; mf < 2; mf++)
#pragma unroll
        for (int nt = 0; nt < 8; nt++)
#pragma unroll
            for (int e = 0; e < 4; e++) oacc[mf][nt][e] = 0.f;
    float l00 = 0.f, l01 = 0.f, l10 = 0.f, l11 = 0.f;

    const uint32_t* Kg = g_Kpk + (size_t)bh * 65536 + lane * 4;
    const uint32_t* Vg = g_Vpk + (size_t)bh * 65536 + lane * 4;

    const float* Eb0 = edges + (size_t)(i0 + 32 * w + g) * NN;
    const float* Eb1 = Eb0 + 8 * NN;
    const float* Eb2 = Eb0 + 16 * NN;
    const float* Eb3 = Eb0 + 24 * NN;

    for (int jt = 0; jt < 16; jt++) {
        const int j0 = jt * 64;
        const uint32_t* Kt = Kg + jt * 4096;
        const uint32_t* Vt = Vg + jt * 4096;

        // ---- Phase 1: MMA1, all 8 j-groups, LDG.128 B-frags ----
        float sacc[2][8][4];
#pragma unroll
        for (int mf = 0; mf < 2; mf++)
#pragma unroll
            for (int jg = 0; jg < 8; jg++)
#pragma unroll
                for (int e = 0; e < 4; e++) sacc[mf][jg][e] = 0.f;
#pragma unroll
        for (int kt2 = 0; kt2 < 4; kt2++) {
#pragma unroll
            for (int jg = 0; jg < 8; jg++) {
                uint4 b4 = *(const uint4*)&Kt[(jg * 4 + kt2) * 128];
                mma8(sacc[0][jg], qa[0][2 * kt2 + 0], b4.x, b4.y);
                mma8(sacc[1][jg], qa[1][2 * kt2 + 0], b4.x, b4.y);
                mma8(sacc[0][jg], qa[0][2 * kt2 + 1], b4.z, b4.w);
                mma8(sacc[1][jg], qa[1][2 * kt2 + 1], b4.z, b4.w);
            }
        }

        // ---- Phase 2: epilogue, in-place convert sacc -> A-frag bits ----
#pragma unroll
        for (int jg = 0; jg < 8; jg++) {
            const int ecol = j0 + jg * 8 + 2 * c;
            {
                float2 e0 = *(const float2*)(Eb0 + ecol);
                float2 e1 = *(const float2*)(Eb1 + ecol);
                float p00 = ex2f(fmaf(e0.x, rbl2e, sacc[0][jg][0]));
                float p01 = ex2f(fmaf(e0.y, rbl2e, sacc[0][jg][1]));
                float p10 = ex2f(fmaf(e1.x, rbl2e, sacc[0][jg][2]));
                float p11 = ex2f(fmaf(e1.y, rbl2e, sacc[0][jg][3]));
                l00 += p00 + p01;
                l01 += p10 + p11;
                sacc[0][jg][0] = __uint_as_float(f2tf(p00));
                sacc[0][jg][1] = __uint_as_float(f2tf(p10));
                sacc[0][jg][2] = __uint_as_float(f2tf(p01));
                sacc[0][jg][3] = __uint_as_float(f2tf(p11));
            }
            {
                float2 e0 = *(const float2*)(Eb2 + ecol);
                float2 e1 = *(const float2*)(Eb3 + ecol);
                float p00 = ex2f(fmaf(e0.x, rbl2e, sacc[1][jg][0]));
                float p01 = ex2f(fmaf(e0.y, rbl2e, sacc[1][jg][1]));
                float p10 = ex2f(fmaf(e1.x, rbl2e, sacc[1][jg][2]));
                float p11 = ex2f(fmaf(e1.y, rbl2e, sacc[1][jg][3]));
                l10 += p00 + p01;
                l11 += p10 + p11;
                sacc[1][jg][0] = __uint_as_float(f2tf(p00));
                sacc[1][jg][1] = __uint_as_float(f2tf(p10));
                sacc[1][jg][2] = __uint_as_float(f2tf(p01));
                sacc[1][jg][3] = __uint_as_float(f2tf(p11));
            }
        }

        // ---- Phase 3: MMA2 over jg, LDG.128 B-frags ----
#pragma unroll
        for (int jg = 0; jg < 8; jg++) {
            const uint32_t* a0 = (const uint32_t*)sacc[0][jg];
            const uint32_t* a1 = (const uint32_t*)sacc[1][jg];
#pragma unroll
            for (int nt2 = 0; nt2 < 4; nt2++) {
                uint4 b4 = *(const uint4*)&Vt[(jg * 4 + nt2) * 128];
                mma8(oacc[0][2 * nt2 + 0], a0, b4.x, b4.y);
                mma8(oacc[1][2 * nt2 + 0], a1, b4.x, b4.y);
                mma8(oacc[0][2 * nt2 + 1], a0, b4.z, b4.w);
                mma8(oacc[1][2 * nt2 + 1], a1, b4.z, b4.w);
            }
        }
    }

    // ---- finalize ----
    l00 += __shfl_xor_sync(0xFFFFFFFF, l00, 1);
    l00 += __shfl_xor_sync(0xFFFFFFFF, l00, 2);
    l01 += __shfl_xor_sync(0xFFFFFFFF, l01, 1);
    l01 += __shfl_xor_sync(0xFFFFFFFF, l01, 2);
    l10 += __shfl_xor_sync(0xFFFFFFFF, l10, 1);
    l10 += __shfl_xor_sync(0xFFFFFFFF, l10, 2);
    l11 += __shfl_xor_sync(0xFFFFFFFF, l11, 1);
    l11 += __shfl_xor_sync(0xFFFFFFFF, l11, 2);
    const float inv[2][2] = {{1.0f / l00, 1.0f / l01}, {1.0f / l10, 1.0f / l11}};

#pragma unroll
    for (int mf = 0; mf < 2; mf++) {
        const int rowb = i0 + 32 * w + 16 * mf;
        uint32_t* O0 = g_Attu + ((size_t)(rowb + g) * BB + b) * EE + h * DD;
        uint32_t* O1 = O0 + (size_t)8 * BB * EE;
#pragma unroll
        for (int nt = 0; nt < 8; nt++) {
            *(uint2*)(O0 + 8 * nt + 2 * c) = make_uint2(
                f2tf(oacc[mf][nt][0] * inv[mf][0]), f2tf(oacc[mf][nt][1] * inv[mf][0]));
            *(uint2*)(O1 + 8 * nt + 2 * c) = make_uint2(
                f2tf(oacc[mf][nt][2] * inv[mf][1]), f2tf(oacc[mf][nt][3] * inv[mf][1]));
        }
    }
}

// ===========================================================================
// Output GEMM: R9 form (128x128 tiles, 256 thr, LDS.64 B-frags, 1 barrier)
// ===========================================================================
#define GST 36
#define OUT_BYTES ((2 * 128 * GST + 2 * 4096) * 4)

__global__ void __launch_bounds__(256) gemm_out(
    const float* __restrict__ bo, float* __restrict__ outp)
{
    extern __shared__ uint32_t s[];
    uint32_t* Ab = s;
    uint32_t* Bb = s + 2 * 128 * GST;

    const int tid  = threadIdx.x;
    const int c0   = blockIdx.y * 128, c0t = blockIdx.y * 16;
    const int r0   = blockIdx.x * 128;
    const uint32_t* __restrict__ Wg = g_Wpk + 3 * 262144;

    const int w = tid >> 5, lane = tid & 31;
    const int g = lane >> 2, c = lane & 3;
    const int wm = w & 3, wn = w >> 2;
    const int srow = tid >> 3, sq4 = tid & 7;

    auto stage = [&](int kc, int buf) {
        const uint32_t ab = smaddr(Ab) + buf * (128 * GST * 4);
        const uint32_t bb = smaddr(Bb) + buf * 16384;
#pragma unroll
        for (int u = 0; u < 4; u++) {
            const int row = u * 32 + srow;
            cpa16(ab + (row * GST + sq4 * 4) * 4,
                  g_Attu + (size_t)(r0 + row) * 512 + kc * 32 + sq4 * 4);
            const int ua = u * 256 + tid;
            const int sb = ua >> 6, ob = ua & 63;
            cpa16(bb + ua * 16,
                  Wg + ((size_t)(c0t + sb) * 64 + kc * 4) * 64 + ob * 4);
        }
        CPA_COMMIT();
    };

    float acc[2][8][4];
#pragma unroll
    for (int mf = 0; mf < 2; mf++)
#pragma unroll
        for (int nt = 0; nt < 8; nt++)
#pragma unroll
            for (int e = 0; e < 4; e++) acc[mf][nt][e] = 0.f;

    stage(0, 0);

    for (int kc = 0; kc < 16; kc++) {
        CPA_WAIT0();
        __syncthreads();
        if (kc < 15) stage(kc + 1, (kc + 1) & 1);

        const uint32_t* As = Ab + (kc & 1) * (128 * GST);
        const uint32_t* Bs = Bb + (kc & 1) * 4096;
#pragma unroll
        for (int kt = 0; kt < 4; kt++) {
            uint32_t a[2][4];
#pragma unroll
            for (int mf = 0; mf < 2; mf++) {
                const int rr = 32 * wm + 16 * mf;
                a[mf][0] = As[(rr + g) * GST + 8 * kt + c];
                a[mf][1] = As[(rr + g + 8) * GST + 8 * kt + c];
                a[mf][2] = As[(rr + g) * GST + 8 * kt + c + 4];
                a[mf][3] = As[(rr + g + 8) * GST + 8 * kt + c + 4];
            }
#pragma unroll
            for (int nt = 0; nt < 8; nt++) {
                uint2 bb = *(const uint2*)&Bs[((wn * 8 + nt) * 4 + kt) * 64 + lane * 2];
                mma8(acc[0][nt], a[0], bb.x, bb.y);
                mma8(acc[1][nt], a[1], bb.x, bb.y);
            }
        }
    }

#pragma unroll
    for (int nt = 0; nt < 8; nt++) {
        const int col = c0 + 64 * wn + 8 * nt + 2 * c;
        float2 bb = *(const float2*)&bo[col & 511];
#pragma unroll
        for (int mf = 0; mf < 2; mf++) {
#pragma unroll
            for (int rh = 0; rh < 2; rh++) {
                const int row = r0 + 32 * wm + 16 * mf + g + 8 * rh;
                float2 v = make_float2(acc[mf][nt][2 * rh] + bb.x,
                                       acc[mf][nt][2 * rh + 1] + bb.y);
                *(float2*)&outp[(size_t)row * 512 + col] = v;
            }
        }
    }
}

// ===========================================================================
extern "C" void kernel_launch(void* const* d_in, const int* in_sizes, int n_in,
                              void* d_out, int out_size)
{
    const float* nodes = (const float*)d_in[0];
    const float* edges = (const float*)d_in[1];
    const float* Wq    = (const float*)d_in[2];
    const float* bq    = (const float*)d_in[3];
    const float* Wk    = (const float*)d_in[4];
    const float* bk    = (const float*)d_in[5];
    const float* Wv    = (const float*)d_in[6];
    const float* bv    = (const float*)d_in[7];
    const float* rel   = (const float*)d_in[8];
    const float* Wo    = (const float*)d_in[9];
    const float* bo    = (const float*)d_in[10];
    float* out = (float*)d_out;

    cudaFuncSetAttribute(gemm_qkv, cudaFuncAttributeMaxDynamicSharedMemorySize, QKV_BYTES);
    cudaFuncSetAttribute(gemm_out, cudaFuncAttributeMaxDynamicSharedMemorySize, OUT_BYTES);

    prepack_A<<<4096, 256>>>(nodes);
    prepack_W<<<dim3(512, 4), 256>>>(Wq, Wk, Wv, Wo);

    gemm_qkv<<<dim3(64, 12), 256, QKV_BYTES>>>(bq, bk, bv);

    attn_mma<<<dim3(NN / 128, BB * HH), 128>>>(edges, rel);

    gemm_out<<<dim3(64, 4), 256, OUT_BYTES>>>(bo, out);
}

// round 16
// speedup vs baseline: 2.2842x; 2.2842x over previous
#include <cuda_runtime.h>
#include <cstdint>

#define NN 1024
#define BB 8
#define EE 512
#define HH 8
#define DD 64
#define L2E 1.4426950408889634f
#define QS (L2E * 0.125f)

// Scratch (device globals: allocation-free per harness rules)
__device__ uint32_t g_Apk[8192 * 512];        // nodes, A-frag packed tf32
__device__ uint32_t g_Wpk[4 * 262144];        // W*, B-frag packed (unpaired)
__device__ uint32_t g_Qu [BB * HH * NN * DD]; // Q tf32, prescaled, [bh][n][d]
__device__ uint32_t g_Kpk[BB * HH * 65536];   // K B-frag packed (unpaired)
__device__ uint32_t g_Vpk[BB * HH * 65536];   // V B-frag packed, j-permuted
__device__ uint32_t g_Attu[NN * BB * EE];     // attn out, tf32 bits, [n][b][e]

// ---------------------------------------------------------------------------
// helpers
// ---------------------------------------------------------------------------
__device__ __forceinline__ uint32_t f2tf(float f) {
    uint32_t r;
    asm("cvt.rna.tf32.f32 %0, %1;" : "=r"(r) : "f"(f));
    return r;
}
__device__ __forceinline__ float ex2f(float x) {
    float r;
    asm("ex2.approx.f32 %0, %1;" : "=f"(r) : "f"(x));
    return r;
}
__device__ __forceinline__ void mma8(float* d, const uint32_t* a,
                                     uint32_t b0, uint32_t b1) {
    asm volatile(
        "mma.sync.aligned.m16n8k8.row.col.f32.tf32.tf32.f32 "
        "{%0,%1,%2,%3}, {%4,%5,%6,%7}, {%8,%9}, {%0,%1,%2,%3};"
        : "+f"(d[0]), "+f"(d[1]), "+f"(d[2]), "+f"(d[3])
        : "r"(a[0]), "r"(a[1]), "r"(a[2]), "r"(a[3]), "r"(b0), "r"(b1));
}
__device__ __forceinline__ uint32_t smaddr(const void* p) {
    uint32_t a;
    asm("{ .reg .u64 t; cvta.to.shared.u64 t, %1; cvt.u32.u64 %0, t; }" : "=r"(a) : "l"(p));
    return a;
}
__device__ __forceinline__ void cpa16(uint32_t s, const void* g) {
    asm volatile("cp.async.ca.shared.global [%0], [%1], 16;" :: "r"(s), "l"(g) : "memory");
}
#define CPA_COMMIT() asm volatile("cp.async.commit_group;" ::: "memory")
#define CPA_WAIT0()  asm volatile("cp.async.wait_group 0;" ::: "memory")

// ===========================================================================
// Pre-pack kernels (R8 exact)
// ===========================================================================
__global__ void __launch_bounds__(256) prepack_A(const float* __restrict__ src)
{
    const int t    = blockIdx.x * 256 + threadIdx.x;
    const int lane = t & 31;
    const int tile = t >> 5;
    const int mt = tile >> 6, kt = tile & 63;
    const int g = lane >> 2, c = lane & 3;
    const float* s = src + (size_t)(mt * 16 + g) * 512 + kt * 8 + c;
    uint4 o;
    o.x = f2tf(s[0]);
    o.y = f2tf(s[8 * 512]);
    o.z = f2tf(s[4]);
    o.w = f2tf(s[8 * 512 + 4]);
    *(uint4*)&g_Apk[(size_t)tile * 128 + lane * 4] = o;
}

__global__ void __launch_bounds__(256) prepack_W(
    const float* __restrict__ Wq, const float* __restrict__ Wk,
    const float* __restrict__ Wv, const float* __restrict__ Wo)
{
    const int which = blockIdx.y;
    const float* __restrict__ W =
        which == 0 ? Wq : which == 1 ? Wk : which == 2 ? Wv : Wo;
    const int t    = blockIdx.x * 256 + threadIdx.x;
    const int lane = t & 31;
    const int tile = t >> 5;
    const int nt = tile >> 6, kt = tile & 63;
    const int g = lane >> 2, c = lane & 3;
    const float* s = W + (size_t)(nt * 8 + g) * 512 + kt * 8 + c;
    uint2 o = make_uint2(f2tf(s[0]), f2tf(s[4]));
    *(uint2*)&g_Wpk[(size_t)which * 262144 + tile * 64 + lane * 2] = o;
}

// ===========================================================================
// QKV GEMM: 128x64 tiles, 128 threads (4 warps, each 32 rows x full 64 cols).
// 4 blocks/SM -> 4 independent barrier groups (decoupled stalls).
// Epilogue -> g_Qu / g_Kpk / g_Vpk (R8's unpaired attn layouts).
// ===========================================================================
#define QKV_BYTES 49152   // 2 stages x (A 16KB + B 8KB)

__global__ void __launch_bounds__(128, 4) gemm_qkv(
    const float* __restrict__ bq, const float* __restrict__ bk,
    const float* __restrict__ bv)
{
    extern __shared__ uint32_t s[];
    const int tid   = threadIdx.x;
    const int which = blockIdx.y >> 3;              // 0..2
    const int c0t   = (blockIdx.y & 7) * 8;         // B n-subtile base (8 cols each)
    const int r0t   = blockIdx.x * 8;               // A m-subtile base (16 rows each)
    const uint32_t* __restrict__ Wg = g_Wpk + (size_t)which * 262144;
    const float* __restrict__ bias = which == 0 ? bq : which == 1 ? bk : bv;

    const int w = tid >> 5, lane = tid & 31;
    const int g = lane >> 2, c = lane & 3;
    const int wm = w;                               // warp owns rows [32w, 32w+32)

    // stage chunk kc: A = 8 m-subtiles x 4 kt x 128 w (16KB), B = 8 n-subtiles
    // x 4 kt x 64 w (8KB). Per-subtile gmem regions are contiguous.
    auto stage = [&](int kc, int buf) {
        const uint32_t ab = smaddr(s) + buf * 24576;
        const uint32_t bb = ab + 16384;
#pragma unroll
        for (int u = 0; u < 8; u++) {               // A: 1024 chunks of 16B
            const int ch = u * 128 + tid;
            const int sa = ch >> 7, off = ch & 127;
            cpa16(ab + ch * 16,
                  g_Apk + ((size_t)(r0t + sa) * 64 + kc * 4) * 128 + off * 4);
        }
#pragma unroll
        for (int u = 0; u < 4; u++) {               // B: 512 chunks of 16B
            const int ch = u * 128 + tid;
            const int sb = ch >> 6, off = ch & 63;
            cpa16(bb + ch * 16,
                  Wg + ((size_t)(c0t + sb) * 64 + kc * 4) * 64 + off * 4);
        }
        CPA_COMMIT();
    };

    float acc[2][8][4];
#pragma unroll
    for (int mf = 0; mf < 2; mf++)
#pragma unroll
        for (int nt = 0; nt < 8; nt++)
#pragma unroll
            for (int e = 0; e < 4; e++) acc[mf][nt][e] = 0.f;

    stage(0, 0);

    for (int kc = 0; kc < 16; kc++) {
        CPA_WAIT0();
        __syncthreads();
        if (kc < 15) stage(kc + 1, (kc + 1) & 1);

        const uint32_t* As = s + (kc & 1) * 6144;
        const uint32_t* Bs = As + 4096;
#pragma unroll
        for (int kt = 0; kt < 4; kt++) {
            uint4 a0 = *(const uint4*)&As[((wm * 2 + 0) * 4 + kt) * 128 + lane * 4];
            uint4 a1 = *(const uint4*)&As[((wm * 2 + 1) * 4 + kt) * 128 + lane * 4];
#pragma unroll
            for (int nt = 0; nt < 8; nt++) {
                uint2 bb = *(const uint2*)&Bs[(nt * 4 + kt) * 64 + lane * 2];
                mma8(acc[0][nt], (const uint32_t*)&a0, bb.x, bb.y);
                mma8(acc[1][nt], (const uint32_t*)&a1, bb.x, bb.y);
            }
        }
    }

    const int r0 = r0t * 16, c0 = c0t * 8;          // c0 in [0,512)
#pragma unroll
    for (int nt = 0; nt < 8; nt++) {
        const int col = c0 + 8 * nt + 2 * c;
        float2 bb = *(const float2*)&bias[col];
#pragma unroll
        for (int mf = 0; mf < 2; mf++) {
#pragma unroll
            for (int rh = 0; rh < 2; rh++) {
                const int row = r0 + 32 * wm + 16 * mf + g + 8 * rh;
                float2 v = make_float2(acc[mf][nt][2 * rh] + bb.x,
                                       acc[mf][nt][2 * rh + 1] + bb.y);
                const int i = row >> 3, bq2 = row & 7;
                const int hh = col >> 6, d = col & 63;
                if (which == 0) {
                    uint2 t = make_uint2(f2tf(v.x * QS), f2tf(v.y * QS));
                    *(uint2*)&g_Qu[(((size_t)(bq2 * HH + hh)) * NN + i) * DD + d] = t;
                } else if (which == 1) {
                    // K packed (R8): lane=(i&7)*4+(d&3), comp=(d>>2)&1
                    uint32_t* dst = g_Kpk + (size_t)(bq2 * HH + hh) * 65536;
                    uint32_t w0 = (uint32_t)(((i >> 3) * 8 + (d >> 3)) * 64
                                 + ((i & 7) * 4 + (d & 3)) * 2 + ((d >> 2) & 1));
                    dst[w0]     = f2tf(v.x);
                    dst[w0 + 2] = f2tf(v.y);
                } else {
                    // V packed j-perm (R8): lane=(d&7)*4+((i&7)>>1), comp=(i&1)
                    uint32_t* dst = g_Vpk + (size_t)(bq2 * HH + hh) * 65536;
                    uint32_t w0 = (uint32_t)(((i >> 3) * 8 + (d >> 3)) * 64
                                 + ((d & 7) * 4 + ((i & 7) >> 1)) * 2 + (i & 1));
                    dst[w0]     = f2tf(v.x);
                    dst[w0 + 8] = f2tf(v.y);
                }
            }
        }
    }
}

// ===========================================================================
// Attention: R8 EXACT (best measured 115.0-115.5us).
// ===========================================================================
#define ATT_BYTES 65536

__global__ void __launch_bounds__(128) attn_mma(
    const float* __restrict__ edges, const float* __restrict__ rel)
{
    extern __shared__ uint32_t sm[];

    const int tid  = threadIdx.x;
    const int w    = tid >> 5;
    const int lane = tid & 31;
    const int g    = lane >> 2;
    const int c    = lane & 3;
    const int bh   = blockIdx.y, b = bh >> 3, h = bh & 7;
    const int i0   = blockIdx.x * 128;
    const float rbl2e = rel[h] * L2E;

    const uint32_t* Qb = g_Qu + ((size_t)bh * NN + i0 + 32 * w) * DD;
    uint32_t qa[2][8][4];
#pragma unroll
    for (int mf = 0; mf < 2; mf++) {
        const uint32_t* Qm = Qb + 16 * mf * DD;
#pragma unroll
        for (int kt = 0; kt < 8; kt++) {
            qa[mf][kt][0] = Qm[g * 64 + 8 * kt + c];
            qa[mf][kt][1] = Qm[(g + 8) * 64 + 8 * kt + c];
            qa[mf][kt][2] = Qm[g * 64 + 8 * kt + c + 4];
            qa[mf][kt][3] = Qm[(g + 8) * 64 + 8 * kt + c + 4];
        }
    }

    float oacc[2][8][4];
#pragma unroll
    for (int mf = 0; mf < 2; mf++)
#pragma unroll
        for (int nt = 0; nt < 8; nt++)
#pragma unroll
            for (int e = 0; e < 4; e++) oacc[mf][nt][e] = 0.f;
    float l00 = 0.f, l01 = 0.f, l10 = 0.f, l11 = 0.f;

    const uint32_t* Kg = g_Kpk + (size_t)bh * 65536;
    const uint32_t* Vg = g_Vpk + (size_t)bh * 65536;

    auto stageKV = [&](int jt, int s) {
        const uint32_t kb = smaddr(sm) + s * 32768;
        const uint32_t vb = kb + 16384;
        const uint32_t* Kt = Kg + jt * 4096;
        const uint32_t* Vt = Vg + jt * 4096;
#pragma unroll
        for (int u = 0; u < 8; u++) {
            const int ch = u * 128 + tid;
            cpa16(kb + ch * 16, Kt + ch * 4);
            cpa16(vb + ch * 16, Vt + ch * 4);
        }
        CPA_COMMIT();
    };

    stageKV(0, 0);

    const float* Eb0 = edges + (size_t)(i0 + 32 * w + g) * NN;
    const float* Eb1 = Eb0 + 8 * NN;
    const float* Eb2 = Eb0 + 16 * NN;
    const float* Eb3 = Eb0 + 24 * NN;

    for (int jt = 0; jt < 16; jt++) {
        const int j0 = jt * 64;
        CPA_WAIT0();
        __syncthreads();

        if (jt < 15) stageKV(jt + 1, (jt + 1) & 1);

        const uint32_t* Ks = sm + (jt & 1) * 8192;
        const uint32_t* Vs = Ks + 4096;
        const int lw = lane * 2;

        // ---- Phase 1: MMA1 for all 8 j-groups (16 independent chains) ----
        float sacc[2][8][4];
#pragma unroll
        for (int mf = 0; mf < 2; mf++)
#pragma unroll
            for (int jg = 0; jg < 8; jg++)
#pragma unroll
                for (int e = 0; e < 4; e++) sacc[mf][jg][e] = 0.f;
#pragma unroll
        for (int kt = 0; kt < 8; kt++) {
#pragma unroll
            for (int jg = 0; jg < 8; jg++) {
                uint2 bb = *(const uint2*)&Ks[(jg * 8 + kt) * 64 + lw];
                mma8(sacc[0][jg], qa[0][kt], bb.x, bb.y);
                mma8(sacc[1][jg], qa[1][kt], bb.x, bb.y);
            }
        }

        // ---- Phase 2: epilogue, in-place convert sacc -> A-frag bits ----
#pragma unroll
        for (int jg = 0; jg < 8; jg++) {
            const int ecol = j0 + jg * 8 + 2 * c;
            {
                float2 e0 = *(const float2*)(Eb0 + ecol);
                float2 e1 = *(const float2*)(Eb1 + ecol);
                float p00 = ex2f(fmaf(e0.x, rbl2e, sacc[0][jg][0]));
                float p01 = ex2f(fmaf(e0.y, rbl2e, sacc[0][jg][1]));
                float p10 = ex2f(fmaf(e1.x, rbl2e, sacc[0][jg][2]));
                float p11 = ex2f(fmaf(e1.y, rbl2e, sacc[0][jg][3]));
                l00 += p00 + p01;
                l01 += p10 + p11;
                sacc[0][jg][0] = __uint_as_float(f2tf(p00));
                sacc[0][jg][1] = __uint_as_float(f2tf(p10));
                sacc[0][jg][2] = __uint_as_float(f2tf(p01));
                sacc[0][jg][3] = __uint_as_float(f2tf(p11));
            }
            {
                float2 e0 = *(const float2*)(Eb2 + ecol);
                float2 e1 = *(const float2*)(Eb3 + ecol);
                float p00 = ex2f(fmaf(e0.x, rbl2e, sacc[1][jg][0]));
                float p01 = ex2f(fmaf(e0.y, rbl2e, sacc[1][jg][1]));
                float p10 = ex2f(fmaf(e1.x, rbl2e, sacc[1][jg][2]));
                float p11 = ex2f(fmaf(e1.y, rbl2e, sacc[1][jg][3]));
                l10 += p00 + p01;
                l11 += p10 + p11;
                sacc[1][jg][0] = __uint_as_float(f2tf(p00));
                sacc[1][jg][1] = __uint_as_float(f2tf(p10));
                sacc[1][jg][2] = __uint_as_float(f2tf(p01));
                sacc[1][jg][3] = __uint_as_float(f2tf(p11));
            }
        }

        // ---- Phase 3: MMA2 over jg (16 independent oacc chains) ----
#pragma unroll
        for (int jg = 0; jg < 8; jg++) {
            const uint32_t* a0 = (const uint32_t*)sacc[0][jg];
            const uint32_t* a1 = (const uint32_t*)sacc[1][jg];
#pragma unroll
            for (int nt = 0; nt < 8; nt++) {
                uint2 bb = *(const uint2*)&Vs[(jg * 8 + nt) * 64 + lw];
                mma8(oacc[0][nt], a0, bb.x, bb.y);
                mma8(oacc[1][nt], a1, bb.x, bb.y);
            }
        }
    }

    // ---- finalize ----
    l00 += __shfl_xor_sync(0xFFFFFFFF, l00, 1);
    l00 += __shfl_xor_sync(0xFFFFFFFF, l00, 2);
    l01 += __shfl_xor_sync(0xFFFFFFFF, l01, 1);
    l01 += __shfl_xor_sync(0xFFFFFFFF, l01, 2);
    l10 += __shfl_xor_sync(0xFFFFFFFF, l10, 1);
    l10 += __shfl_xor_sync(0xFFFFFFFF, l10, 2);
    l11 += __shfl_xor_sync(0xFFFFFFFF, l11, 1);
    l11 += __shfl_xor_sync(0xFFFFFFFF, l11, 2);
    const float inv[2][2] = {{1.0f / l00, 1.0f / l01}, {1.0f / l10, 1.0f / l11}};

#pragma unroll
    for (int mf = 0; mf < 2; mf++) {
        const int rowb = i0 + 32 * w + 16 * mf;
        uint32_t* O0 = g_Attu + ((size_t)(rowb + g) * BB + b) * EE + h * DD;
        uint32_t* O1 = O0 + (size_t)8 * BB * EE;
#pragma unroll
        for (int nt = 0; nt < 8; nt++) {
            *(uint2*)(O0 + 8 * nt + 2 * c) = make_uint2(
                f2tf(oacc[mf][nt][0] * inv[mf][0]), f2tf(oacc[mf][nt][1] * inv[mf][0]));
            *(uint2*)(O1 + 8 * nt + 2 * c) = make_uint2(
                f2tf(oacc[mf][nt][2] * inv[mf][1]), f2tf(oacc[mf][nt][3] * inv[mf][1]));
        }
    }
}

// ===========================================================================
// Output GEMM: R8 exact (128x128, 256 thr, two-barrier pipelined loop)
// ===========================================================================
#define GST 36
#define OUT_BYTES ((2 * 128 * GST + 2 * 4096) * 4)

__global__ void __launch_bounds__(256) gemm_out(
    const float* __restrict__ bo, float* __restrict__ outp)
{
    extern __shared__ uint32_t s[];
    uint32_t* Ab = s;
    uint32_t* Bb = s + 2 * 128 * GST;

    const int tid  = threadIdx.x;
    const int c0   = blockIdx.y * 128, c0t = blockIdx.y * 16;
    const int r0   = blockIdx.x * 128;
    const uint32_t* __restrict__ Wg = g_Wpk + 3 * 262144;

    const int w = tid >> 5, lane = tid & 31;
    const int g = lane >> 2, c = lane & 3;
    const int wm = w & 3, wn = w >> 2;
    const int srow = tid >> 3, sq4 = tid & 7;

    auto stage = [&](int kc, int buf) {
        const uint32_t ab = smaddr(Ab) + buf * (128 * GST * 4);
        const uint32_t bb = smaddr(Bb) + buf * 16384;
#pragma unroll
        for (int u = 0; u < 4; u++) {
            const int row = u * 32 + srow;
            cpa16(ab + (row * GST + sq4 * 4) * 4,
                  g_Attu + (size_t)(r0 + row) * 512 + kc * 32 + sq4 * 4);
            const int ua = u * 256 + tid;
            const int sb = ua >> 6, ob = ua & 63;
            cpa16(bb + ua * 16,
                  Wg + ((size_t)(c0t + sb) * 64 + kc * 4) * 64 + ob * 4);
        }
        CPA_COMMIT();
    };

    float acc[2][8][4];
#pragma unroll
    for (int mf = 0; mf < 2; mf++)
#pragma unroll
        for (int nt = 0; nt < 8; nt++)
#pragma unroll
            for (int e = 0; e < 4; e++) acc[mf][nt][e] = 0.f;

    stage(0, 0);

    for (int kc = 0; kc < 16; kc++) {
        CPA_WAIT0();
        __syncthreads();
        if (kc < 15) stage(kc + 1, (kc + 1) & 1);

        const uint32_t* As = Ab + (kc & 1) * (128 * GST);
        const uint32_t* Bs = Bb + (kc & 1) * 4096;
#pragma unroll
        for (int kt = 0; kt < 4; kt++) {
            uint32_t a[2][4];
#pragma unroll
            for (int mf = 0; mf < 2; mf++) {
                const int rr = 32 * wm + 16 * mf;
                a[mf][0] = As[(rr + g) * GST + 8 * kt + c];
                a[mf][1] = As[(rr + g + 8) * GST + 8 * kt + c];
                a[mf][2] = As[(rr + g) * GST + 8 * kt + c + 4];
                a[mf][3] = As[(rr + g + 8) * GST + 8 * kt + c + 4];
            }
#pragma unroll
            for (int nt = 0; nt < 8; nt++) {
                uint2 bb = *(const uint2*)&Bs[((wn * 8 + nt) * 4 + kt) * 64 + lane * 2];
                mma8(acc[0][nt], a[0], bb.x, bb.y);
                mma8(acc[1][nt], a[1], bb.x, bb.y);
            }
        }
    }

#pragma unroll
    for (int nt = 0; nt < 8; nt++) {
        const int col = c0 + 64 * wn + 8 * nt + 2 * c;
        float2 bb = *(const float2*)&bo[col & 511];
#pragma unroll
        for (int mf = 0; mf < 2; mf++) {
#pragma unroll
            for (int rh = 0; rh < 2; rh++) {
                const int row = r0 + 32 * wm + 16 * mf + g + 8 * rh;
                float2 v = make_float2(acc[mf][nt][2 * rh] + bb.x,
                                       acc[mf][nt][2 * rh + 1] + bb.y);
                *(float2*)&outp[(size_t)row * 512 + col] = v;
            }
        }
    }
}

// ===========================================================================
extern "C" void kernel_launch(void* const* d_in, const int* in_sizes, int n_in,
                              void* d_out, int out_size)
{
    const float* nodes = (const float*)d_in[0];
    const float* edges = (const float*)d_in[1];
    const float* Wq    = (const float*)d_in[2];
    const float* bq    = (const float*)d_in[3];
    const float* Wk    = (const float*)d_in[4];
    const float* bk    = (const float*)d_in[5];
    const float* Wv    = (const float*)d_in[6];
    const float* bv    = (const float*)d_in[7];
    const float* rel   = (const float*)d_in[8];
    const float* Wo    = (const float*)d_in[9];
    const float* bo    = (const float*)d_in[10];
    float* out = (float*)d_out;

    cudaFuncSetAttribute(attn_mma, cudaFuncAttributeMaxDynamicSharedMemorySize, ATT_BYTES);
    cudaFuncSetAttribute(gemm_qkv, cudaFuncAttributeMaxDynamicSharedMemorySize, QKV_BYTES);
    cudaFuncSetAttribute(gemm_out, cudaFuncAttributeMaxDynamicSharedMemorySize, OUT_BYTES);

    prepack_A<<<4096, 256>>>(nodes);
    prepack_W<<<dim3(512, 4), 256>>>(Wq, Wk, Wv, Wo);

    // 128x64 tiles: grid (64 row-tiles, 3 weights x 8 col-tiles)
    gemm_qkv<<<dim3(64, 24), 128, QKV_BYTES>>>(bq, bk, bv);

    attn_mma<<<dim3(NN / 128, BB * HH), 128, ATT_BYTES>>>(edges, rel);

    gemm_out<<<dim3(64, 4), 256, OUT_BYTES>>>(bo, out);
}